// round 16
// baseline (speedup 1.0000x reference)
#include <cuda_runtime.h>
#include <cuda_bf16.h>
#include <cuda_fp16.h>
#include <math.h>
#include <stdint.h>

typedef unsigned int u32;

#define Bc   4
#define NQc  2048
#define NKc  2048
#define Dc   1024
#define Hc   8
#define DKc  128
#define DVc  128
#define DOc  1024
#define HBc  32

__device__ float g_qh  [(size_t)Bc*NQc*Hc*DKc];
__device__ float g_kh  [(size_t)Bc*NKc*DKc];
__device__ float g_vh  [(size_t)Bc*NKc*DVc];
__device__ float g_outh[(size_t)Bc*NQc*Hc*DVc];
__device__ float g_vT  [(size_t)Bc*DVc*NKc];

// ---------------- helpers ---------------------------------------------------
__device__ __forceinline__ u32 s2u(const void* p){
    u32 a; asm("{ .reg .u64 t; cvta.to.shared.u64 t, %1; cvt.u32.u64 %0, t; }"
               : "=r"(a) : "l"(p)); return a;
}
__device__ __forceinline__ u32 pkbf2(float a, float b){
    u32 ra = (u32)__bfloat16_as_ushort(__float2bfloat16(a));
    u32 rb = (u32)__bfloat16_as_ushort(__float2bfloat16(b));
    return ra | (rb << 16);
}
__device__ __forceinline__ float bres(float x){
    return x - __bfloat162float(__float2bfloat16(x));
}
__device__ __forceinline__ u32 pkhf2(float a, float b){
    __half2 h = __floats2half2_rn(a, b);
    return *(u32*)&h;
}
__device__ __forceinline__ float hres(float x){
    return x - __half2float(__float2half_rn(x));
}
__device__ __forceinline__ void ldmx4(u32* r, u32 addr){
    asm volatile("ldmatrix.sync.aligned.m8n8.x4.shared.b16 {%0,%1,%2,%3}, [%4];"
        : "=r"(r[0]), "=r"(r[1]), "=r"(r[2]), "=r"(r[3]) : "r"(addr));
}
__device__ __forceinline__ void mma16816(float* c, const u32* a, u32 b0, u32 b1){
    asm volatile("mma.sync.aligned.m16n8k16.row.col.f32.bf16.bf16.f32 "
        "{%0,%1,%2,%3}, {%4,%5,%6,%7}, {%8,%9}, {%0,%1,%2,%3};"
        : "+f"(c[0]), "+f"(c[1]), "+f"(c[2]), "+f"(c[3])
        : "r"(a[0]), "r"(a[1]), "r"(a[2]), "r"(a[3]), "r"(b0), "r"(b1));
}
__device__ __forceinline__ void mma16816h(float* c, const u32* a, u32 b0, u32 b1){
    asm volatile("mma.sync.aligned.m16n8k16.row.col.f32.f16.f16.f32 "
        "{%0,%1,%2,%3}, {%4,%5,%6,%7}, {%8,%9}, {%0,%1,%2,%3};"
        : "+f"(c[0]), "+f"(c[1]), "+f"(c[2]), "+f"(c[3])
        : "r"(a[0]), "r"(a[1]), "r"(a[2]), "r"(a[3]), "r"(b0), "r"(b1));
}

// rows x COLS fp32 -> bf16 hi/lo smem (projection path)
template<int ROWS, int COLS, int STRIDE>
__device__ __forceinline__ void ldconvG(const float* __restrict__ g, int ldA,
                                        char* smHi, char* smLo, int tid){
    const int PER = (ROWS*COLS/4)/256;
#pragma unroll
    for (int i = 0; i < PER; i++){
        int idx = tid + i*256;
        int row = idx / (COLS/4);
        int c4  = (idx % (COLS/4))*4;
        float4 v = *(const float4*)(g + (size_t)row*ldA + c4);
        int off = (row*STRIDE + c4)*2;
        *(uint2*)(smHi+off) = make_uint2(pkbf2(v.x,v.y), pkbf2(v.z,v.w));
        *(uint2*)(smLo+off) = make_uint2(pkbf2(bres(v.x),bres(v.y)),
                                         pkbf2(bres(v.z),bres(v.w)));
    }
}
// rows x COLS fp32 -> fp16 hi+lo smem
template<int ROWS, int COLS, int STRIDE>
__device__ __forceinline__ void ldconvH2(const float* __restrict__ g, int ldA,
                                         char* smHi, char* smLo, int tid){
    const int PER = (ROWS*COLS/4)/256;
#pragma unroll
    for (int i = 0; i < PER; i++){
        int idx = tid + i*256;
        int row = idx / (COLS/4);
        int c4  = (idx % (COLS/4))*4;
        float4 v = *(const float4*)(g + (size_t)row*ldA + c4);
        int off = (row*STRIDE + c4)*2;
        *(uint2*)(smHi+off) = make_uint2(pkhf2(v.x,v.y), pkhf2(v.z,v.w));
        *(uint2*)(smLo+off) = make_uint2(pkhf2(hres(v.x),hres(v.y)),
                                         pkhf2(hres(v.z),hres(v.w)));
    }
}
// rows x COLS fp32 -> fp16 single plane
template<int ROWS, int COLS, int STRIDE>
__device__ __forceinline__ void ldconvH1(const float* __restrict__ g, int ldA,
                                         char* smHi, int tid){
    const int PER = (ROWS*COLS/4)/256;
#pragma unroll
    for (int i = 0; i < PER; i++){
        int idx = tid + i*256;
        int row = idx / (COLS/4);
        int c4  = (idx % (COLS/4))*4;
        float4 v = *(const float4*)(g + (size_t)row*ldA + c4);
        *(uint2*)(smHi + (row*STRIDE + c4)*2) =
            make_uint2(pkhf2(v.x,v.y), pkhf2(v.z,v.w));
    }
}

// 128x128-output warp step (proj, bf16x3): warp computes 32x64
template<int SA, int SB>
__device__ __forceinline__ void wstep(u32 Ah, u32 Al, u32 Bh, u32 Bl,
                                      int ks, int warp_m, int warp_n, int lane,
                                      float c[2][8][4]){
    const int rsel = lane & 15, ksel = (lane >> 4) << 3;
    const int kb = ks*16 + ksel;
    u32 ah[2][4], al[2][4], bh[4][4], bl[4][4];
#pragma unroll
    for (int mt = 0; mt < 2; mt++){
        u32 off = (u32)((warp_m*32 + mt*16 + rsel)*SA + kb)*2;
        ldmx4(ah[mt], Ah + off);
        ldmx4(al[mt], Al + off);
    }
#pragma unroll
    for (int p = 0; p < 4; p++){
        u32 off = (u32)((warp_n*64 + p*16 + rsel)*SB + kb)*2;
        ldmx4(bh[p], Bh + off);
        ldmx4(bl[p], Bl + off);
    }
#pragma unroll
    for (int mt = 0; mt < 2; mt++)
#pragma unroll
        for (int nt = 0; nt < 8; nt++){
            int p = nt >> 1, s = nt & 1;
            mma16816(c[mt][nt], ah[mt], bh[p][s], bh[p][2+s]);
            mma16816(c[mt][nt], ah[mt], bl[p][s], bl[p][2+s]);
            mma16816(c[mt][nt], al[mt], bh[p][s], bh[p][2+s]);
        }
}

// Phase-1 step: out 64q x 64k, warp 16x32. A 16 rows, B 32 rows. fp16 2-term.
template<int SA, int SB>
__device__ __forceinline__ void wstep_s(u32 Ah, u32 Bh, u32 Bl,
                                        int ks, int warp_m, int warp_n, int lane,
                                        float c[4][4]){
    const int rsel = lane & 15, ksel = (lane >> 4) << 3;
    const int kb = ks*16 + ksel;
    u32 ah[4], bh[2][4], bl[2][4];
    ldmx4(ah, Ah + (u32)((warp_m*16 + rsel)*SA + kb)*2);
#pragma unroll
    for (int p = 0; p < 2; p++){
        u32 off = (u32)((warp_n*32 + p*16 + rsel)*SB + kb)*2;
        ldmx4(bh[p], Bh + off);
        ldmx4(bl[p], Bl + off);
    }
#pragma unroll
    for (int nt = 0; nt < 4; nt++){
        int p = nt >> 1, s = nt & 1;
        mma16816h(c[nt], ah, bh[p][s], bh[p][2+s]);
        mma16816h(c[nt], ah, bl[p][s], bl[p][2+s]);
    }
}

// Phase-2 step: out 64q x 128d, warp 16x64. A 16 rows, B 64 rows. fp16 2-term.
template<int SA, int SB>
__device__ __forceinline__ void wstep_v(u32 Ah, u32 Bh, u32 Bl,
                                        int ks, int warp_m, int warp_n, int lane,
                                        float c[8][4]){
    const int rsel = lane & 15, ksel = (lane >> 4) << 3;
    const int kb = ks*16 + ksel;
    u32 ah[4], bh[4][4], bl[4][4];
    ldmx4(ah, Ah + (u32)((warp_m*16 + rsel)*SA + kb)*2);
#pragma unroll
    for (int p = 0; p < 4; p++){
        u32 off = (u32)((warp_n*64 + p*16 + rsel)*SB + kb)*2;
        ldmx4(bh[p], Bh + off);
        ldmx4(bl[p], Bl + off);
    }
#pragma unroll
    for (int nt = 0; nt < 8; nt++){
        int p = nt >> 1, s = nt & 1;
        mma16816h(c[nt], ah, bh[p][s], bh[p][2+s]);
        mma16816h(c[nt], ah, bl[p][s], bl[p][2+s]);
    }
}

// ---------------------------------------------------------------------------
// proj (bf16x3, 2 CTAs/SM, unchanged).
// ---------------------------------------------------------------------------
#define PSTR 72
#define PTILE (128*PSTR*2)
#define PROJ_SM (4*PTILE)
__device__ __forceinline__ void proj_body(
    const float* __restrict__ A, const float* __restrict__ W,
    const float* __restrict__ bias, float* __restrict__ C,
    int M, int N, int K, int m0, int n0, char* sm)
{
    u32 sb = s2u(sm);
    const int tid = threadIdx.x, lane = tid & 31, wid = tid >> 5;
    const int warp_m = wid & 3, warp_n = wid >> 2;

    char* Ahp = sm;            char* Alp = sm + PTILE;
    char* Bhp = sm + 2*PTILE;  char* Blp = sm + 3*PTILE;
    const u32 Ah = sb, Al = sb + PTILE, Bh = sb + 2*PTILE, Bl = sb + 3*PTILE;

    float c[2][8][4];
#pragma unroll
    for (int i=0;i<2;i++) for (int j=0;j<8;j++) for (int q=0;q<4;q++) c[i][j][q]=0.f;

    const int NC = K/64;
    for (int kc = 0; kc < NC; kc++){
        ldconvG<128,64,PSTR>(A + (size_t)m0*K + kc*64, K, Ahp, Alp, tid);
        ldconvG<128,64,PSTR>(W + (size_t)n0*K + kc*64, K, Bhp, Blp, tid);
        __syncthreads();
#pragma unroll
        for (int ks = 0; ks < 4; ks++)
            wstep<PSTR,PSTR>(Ah, Al, Bh, Bl, ks, warp_m, warp_n, lane, c);
        __syncthreads();
    }

#pragma unroll
    for (int mt = 0; mt < 2; mt++)
#pragma unroll
        for (int rh = 0; rh < 2; rh++){
            int row = m0 + warp_m*32 + mt*16 + rh*8 + (lane >> 2);
#pragma unroll
            for (int nt = 0; nt < 8; nt++){
                int col = n0 + warp_n*64 + nt*8 + ((lane & 3) << 1);
                float2 o;
                o.x = c[mt][nt][rh*2+0] + __ldg(bias + col);
                o.y = c[mt][nt][rh*2+1] + __ldg(bias + col + 1);
                *(float2*)(C + (size_t)row*N + col) = o;
            }
        }
}

__global__ void __launch_bounds__(256,2) proj_mma(
    const float* __restrict__ A, const float* __restrict__ W,
    const float* __restrict__ bias, float* __restrict__ C,
    int M, int N, int K)
{
    extern __shared__ char sm[];
    proj_body(A, W, bias, C, M, N, K, blockIdx.y << 7, blockIdx.x << 7, sm);
}

__global__ void __launch_bounds__(256,2) proj_mma_kv(
    const float* __restrict__ kin, const float* __restrict__ vin,
    const float* __restrict__ Wk, const float* __restrict__ bk, float* __restrict__ kh,
    const float* __restrict__ Wv, const float* __restrict__ bv, float* __restrict__ vh,
    int M, int K)
{
    extern __shared__ char sm[];
    if (blockIdx.x == 0)
        proj_body(kin, Wk, bk, kh, M, DKc, K, blockIdx.y << 7, 0, sm);
    else
        proj_body(vin, Wv, bv, vh, M, DVc, K, blockIdx.y << 7, 0, sm);
}

// vh [b,k,d] -> vT [b,d,k]
__global__ void transpose_v(const float* __restrict__ vh, float* __restrict__ vT){
    __shared__ float t[32][33];
    int b = blockIdx.z;
    int k0 = blockIdx.x*32, d0 = blockIdx.y*32;
    int x = threadIdx.x, y = threadIdx.y;
#pragma unroll
    for (int i = 0; i < 32; i += 8)
        t[y+i][x] = vh[(size_t)(b*NKc + k0 + y + i)*DVc + d0 + x];
    __syncthreads();
#pragma unroll
    for (int i = 0; i < 32; i += 8)
        vT[((size_t)b*DVc + d0 + y + i)*NKc + k0 + x] = t[x][y+i];
}

// ---------------------------------------------------------------------------
// fused attention: fp16 2-term, 64-row k-chunks, 3 CTAs/SM.
// Phase 1: S 64q x 64k per chunk (32 chunks). Phase 2: P(64x64) @ V(64x128).
// ---------------------------------------------------------------------------
#define SSTR 136
#define VSTR 72
#define ATILE (64*SSTR*2)     // 17408 (Q 64x128 / P 64x64 region)
#define KBTILE (64*SSTR*2)    // 17408 per plane (K chunk 64x128)
#define VBTILE (128*VSTR*2)   // 18432 per plane (V chunk 128x64)
#define FUS_SM (ATILE + 2*VBTILE)  // 54272 -> 3 CTAs/SM
#define KCH 32                // 2048/64 chunks
__global__ void __launch_bounds__(256,3) fused_attn(
    const float* __restrict__ qh, const float* __restrict__ kh,
    const float* __restrict__ vT, const float* __restrict__ mask,
    float* __restrict__ attn, float* __restrict__ outh)
{
    extern __shared__ char sm[];
    __shared__ float Ms[64], Li[64];
    __shared__ float sM2[2][64], sL2[2][64];
    u32 sb = s2u(sm);
    const int tid = threadIdx.x, lane = tid & 31, wid = tid >> 5;
    const int warp_m = wid & 3, warp_n = wid >> 2;   // 4 x 16 rows, 2 cols-groups
    const int q0 = blockIdx.x << 6;
    const int hb = blockIdx.y, b = hb >> 3, h = hb & 7;

    char* Ahp = sm;                  // Q (64x128, SSTR) / P (64x64, VSTR)
    char* Bhp = sm + ATILE;          // K/V hi
    char* Blp = sm + ATILE + VBTILE; // K/V lo
    const u32 Ah = sb, Bh = sb + ATILE, Bl = sb + ATILE + VBTILE;

    const float* qbase = qh + (size_t)(b*NQc + q0)*Dc + h*DKc;
    const float* kbase = kh + (size_t)b*NKc*DKc;
    const float* vbase = vT + (size_t)b*DVc*NKc;
    float* abase = attn + ((size_t)(h*Bc + b)*NQc + q0)*NKc;

    // ---- Phase 1: S = scale*(Q@K^T)+mask per 64-k chunk ----
    ldconvH1<64,128,SSTR>(qbase, Dc, Ahp, tid);

    const float scale = 0.08838834764831845f;
    float rm_[2] = {-1e30f, -1e30f}, rl_[2] = {0.f, 0.f};

    for (int kt = 0; kt < KCH; kt++){
        ldconvH2<64,128,SSTR>(kbase + (size_t)(kt*64)*DKc, DKc, Bhp, Blp, tid);
        __syncthreads();

        float c[4][4];
#pragma unroll
        for (int j=0;j<4;j++) for (int q=0;q<4;q++) c[j][q]=0.f;
#pragma unroll
        for (int ks = 0; ks < 8; ks++)
            wstep_s<SSTR,SSTR>(Ah, Bh, Bl, ks, warp_m, warp_n, lane, c);

#pragma unroll
        for (int rh = 0; rh < 2; rh++){
            int rowl = warp_m*16 + rh*8 + (lane >> 2);
            const float* mrow = mask + ((size_t)b*NQc + q0 + rowl)*NKc + kt*64;
            float* arow = abase + (size_t)rowl*NKc + kt*64;
            float sv[8];
            float mloc = -1e30f;
#pragma unroll
            for (int nt = 0; nt < 4; nt++){
                int col = warp_n*32 + nt*8 + ((lane & 3) << 1);
                float2 mv = *(const float2*)(mrow + col);
                sv[2*nt+0] = fmaf(c[nt][rh*2+0], scale, mv.x);
                sv[2*nt+1] = fmaf(c[nt][rh*2+1], scale, mv.y);
                *(float2*)(arow + col) = make_float2(sv[2*nt+0], sv[2*nt+1]);
                mloc = fmaxf(mloc, fmaxf(sv[2*nt+0], sv[2*nt+1]));
            }
#pragma unroll
            for (int off = 1; off <= 2; off <<= 1)
                mloc = fmaxf(mloc, __shfl_xor_sync(0xFFFFFFFFu, mloc, off));
            float let = 0.f;
#pragma unroll
            for (int nt = 0; nt < 4; nt++){
                let += __expf(sv[2*nt+0] - mloc);
                let += __expf(sv[2*nt+1] - mloc);
            }
#pragma unroll
            for (int off = 1; off <= 2; off <<= 1)
                let += __shfl_xor_sync(0xFFFFFFFFu, let, off);
            float nm = fmaxf(rm_[rh], mloc);
            rl_[rh] = rl_[rh]*__expf(rm_[rh] - nm) + let*__expf(mloc - nm);
            rm_[rh] = nm;
        }
        __syncthreads();
    }

    // ---- stat combine across 2 warp_n halves ----
#pragma unroll
    for (int rh = 0; rh < 2; rh++){
        int rowl = warp_m*16 + rh*8 + (lane >> 2);
        if ((lane & 3) == 0){
            sM2[warp_n][rowl] = rm_[rh];
            sL2[warp_n][rowl] = rl_[rh];
        }
    }
    __syncthreads();
    if (tid < 64){
        float m0 = sM2[0][tid], m1 = sM2[1][tid];
        float M = fmaxf(m0, m1);
        float L = sL2[0][tid]*__expf(m0 - M) + sL2[1][tid]*__expf(m1 - M);
        Ms[tid] = M; Li[tid] = 1.0f / L;
    }
    __syncthreads();

    // ---- Phase 2: P(64x64) @ V^T-chunk(128d x 64k), 4 k-steps ----
    float c[8][4];
#pragma unroll
    for (int j=0;j<8;j++) for (int q=0;q<4;q++) c[j][q]=0.f;

    for (int kt = 0; kt < KCH; kt++){
        // normalize P chunk 64x64: 1024 float4 / 256 thr = 4 iters
#pragma unroll
        for (int i = 0; i < 4; i++){
            int idx = tid + i*256;
            int row = idx >> 4, c4 = (idx & 15) << 2;
            float* ap = abase + (size_t)row*NKc + kt*64 + c4;
            float4 s = *(float4*)ap;
            float mm = Ms[row], li = Li[row];
            float4 p;
            p.x = __expf(s.x - mm)*li; p.y = __expf(s.y - mm)*li;
            p.z = __expf(s.z - mm)*li; p.w = __expf(s.w - mm)*li;
            *(float4*)ap = p;
            *(uint2*)(Ahp + (row*VSTR + c4)*2) =
                make_uint2(pkhf2(p.x,p.y), pkhf2(p.z,p.w));
        }
        ldconvH2<128,64,VSTR>(vbase + kt*64, NKc, Bhp, Blp, tid);
        __syncthreads();
#pragma unroll
        for (int ks = 0; ks < 4; ks++)
            wstep_v<VSTR,VSTR>(Ah, Bh, Bl, ks, warp_m, warp_n, lane, c);
        __syncthreads();
    }

#pragma unroll
    for (int rh = 0; rh < 2; rh++){
        int row = q0 + warp_m*16 + rh*8 + (lane >> 2);
        float* op = outh + (size_t)(b*NQc + row)*(Hc*DVc) + h*DVc;
#pragma unroll
        for (int nt = 0; nt < 8; nt++){
            int col = warp_n*64 + nt*8 + ((lane & 3) << 1);
            *(float2*)(op + col) = make_float2(c[nt][rh*2+0], c[nt][rh*2+1]);
        }
    }
}

// ---------------------------------------------------------------------------
extern "C" void kernel_launch(void* const* d_in, const int* in_sizes, int n_in,
                              void* d_out, int out_size)
{
    const float* q    = (const float*)d_in[0];
    const float* k    = (const float*)d_in[1];
    const float* v    = (const float*)d_in[2];
    const float* mask = (const float*)d_in[3];
    const float* Wq   = (const float*)d_in[4];
    const float* bq   = (const float*)d_in[5];
    const float* Wk   = (const float*)d_in[6];
    const float* bk   = (const float*)d_in[7];
    const float* Wv   = (const float*)d_in[8];
    const float* bv   = (const float*)d_in[9];
    const float* Wo   = (const float*)d_in[10];
    const float* bo   = (const float*)d_in[11];

    float* attn = (float*)d_out;
    float* outp = attn + (size_t)HBc*NQc*NKc;

    float *qh,*kh,*vh,*vT,*outh;
    cudaGetSymbolAddress((void**)&qh,   g_qh);
    cudaGetSymbolAddress((void**)&kh,   g_kh);
    cudaGetSymbolAddress((void**)&vh,   g_vh);
    cudaGetSymbolAddress((void**)&vT,   g_vT);
    cudaGetSymbolAddress((void**)&outh, g_outh);

    cudaFuncSetAttribute(proj_mma,    cudaFuncAttributeMaxDynamicSharedMemorySize, PROJ_SM);
    cudaFuncSetAttribute(proj_mma_kv, cudaFuncAttributeMaxDynamicSharedMemorySize, PROJ_SM);
    cudaFuncSetAttribute(fused_attn,  cudaFuncAttributeMaxDynamicSharedMemorySize, FUS_SM);

    dim3 blk(256);
    const int Mr = Bc*NQc;   // 8192

    proj_mma<<<dim3((Hc*DKc)/128, Mr/128), blk, PROJ_SM>>>(q, Wq, bq, qh, Mr, Hc*DKc, Dc);
    proj_mma_kv<<<dim3(2, Mr/128), blk, PROJ_SM>>>(k, v, Wk, bk, kh, Wv, bv, vh, Mr, Dc);

    transpose_v<<<dim3(NKc/32, DVc/32, Bc), dim3(32,8)>>>(vh, vT);

    fused_attn<<<dim3(NQc/64, HBc), blk, FUS_SM>>>(qh, kh, vT, mask, attn, outh);

    proj_mma<<<dim3(DOc/128, Mr/128), blk, PROJ_SM>>>(outh, Wo, bo, outp, Mr, DOc, Hc*DVc);
}

// round 17
// speedup vs baseline: 1.0547x; 1.0547x over previous
#include <cuda_runtime.h>
#include <cuda_bf16.h>
#include <cuda_fp16.h>
#include <math.h>
#include <stdint.h>

typedef unsigned int u32;

#define Bc   4
#define NQc  2048
#define NKc  2048
#define Dc   1024
#define Hc   8
#define DKc  128
#define DVc  128
#define DOc  1024
#define HBc  32
#define KTILES 16

__device__ float g_qh  [(size_t)Bc*NQc*Hc*DKc];
__device__ float g_kh  [(size_t)Bc*NKc*DKc];
__device__ float g_vh  [(size_t)Bc*NKc*DVc];
__device__ float g_outh[(size_t)Bc*NQc*Hc*DVc];
__device__ float g_vT  [(size_t)Bc*DVc*NKc];

// ---------------- helpers ---------------------------------------------------
__device__ __forceinline__ u32 s2u(const void* p){
    u32 a; asm("{ .reg .u64 t; cvta.to.shared.u64 t, %1; cvt.u32.u64 %0, t; }"
               : "=r"(a) : "l"(p)); return a;
}
__device__ __forceinline__ u32 pkbf2(float a, float b){
    u32 ra = (u32)__bfloat16_as_ushort(__float2bfloat16(a));
    u32 rb = (u32)__bfloat16_as_ushort(__float2bfloat16(b));
    return ra | (rb << 16);
}
__device__ __forceinline__ float bres(float x){
    return x - __bfloat162float(__float2bfloat16(x));
}
__device__ __forceinline__ u32 pkhf2(float a, float b){
    __half2 h = __floats2half2_rn(a, b);
    return *(u32*)&h;
}
__device__ __forceinline__ float hres(float x){
    return x - __half2float(__float2half_rn(x));
}
__device__ __forceinline__ void ldmx4(u32* r, u32 addr){
    asm volatile("ldmatrix.sync.aligned.m8n8.x4.shared.b16 {%0,%1,%2,%3}, [%4];"
        : "=r"(r[0]), "=r"(r[1]), "=r"(r[2]), "=r"(r[3]) : "r"(addr));
}
__device__ __forceinline__ void mma16816(float* c, const u32* a, u32 b0, u32 b1){
    asm volatile("mma.sync.aligned.m16n8k16.row.col.f32.bf16.bf16.f32 "
        "{%0,%1,%2,%3}, {%4,%5,%6,%7}, {%8,%9}, {%0,%1,%2,%3};"
        : "+f"(c[0]), "+f"(c[1]), "+f"(c[2]), "+f"(c[3])
        : "r"(a[0]), "r"(a[1]), "r"(a[2]), "r"(a[3]), "r"(b0), "r"(b1));
}
__device__ __forceinline__ void mma16816h(float* c, const u32* a, u32 b0, u32 b1){
    asm volatile("mma.sync.aligned.m16n8k16.row.col.f32.f16.f16.f32 "
        "{%0,%1,%2,%3}, {%4,%5,%6,%7}, {%8,%9}, {%0,%1,%2,%3};"
        : "+f"(c[0]), "+f"(c[1]), "+f"(c[2]), "+f"(c[3])
        : "r"(a[0]), "r"(a[1]), "r"(a[2]), "r"(a[3]), "r"(b0), "r"(b1));
}

// rows x COLS fp32 -> bf16 hi/lo smem (projection path)
template<int ROWS, int COLS, int STRIDE>
__device__ __forceinline__ void ldconvG(const float* __restrict__ g, int ldA,
                                        char* smHi, char* smLo, int tid){
    const int PER = (ROWS*COLS/4)/256;
#pragma unroll
    for (int i = 0; i < PER; i++){
        int idx = tid + i*256;
        int row = idx / (COLS/4);
        int c4  = (idx % (COLS/4))*4;
        float4 v = *(const float4*)(g + (size_t)row*ldA + c4);
        int off = (row*STRIDE + c4)*2;
        *(uint2*)(smHi+off) = make_uint2(pkbf2(v.x,v.y), pkbf2(v.z,v.w));
        *(uint2*)(smLo+off) = make_uint2(pkbf2(bres(v.x),bres(v.y)),
                                         pkbf2(bres(v.z),bres(v.w)));
    }
}
// rows x 128 fp32 -> fp16 hi+lo smem (fused K operand)
template<int ROWS, int STRIDE>
__device__ __forceinline__ void ldconvH2(const float* __restrict__ g, int ldA,
                                         char* smHi, char* smLo, int tid){
    const int PER = (ROWS*32)/256;
#pragma unroll
    for (int i = 0; i < PER; i++){
        int idx = tid + i*256;
        int row = idx >> 5;
        int c4  = (idx & 31) << 2;
        float4 v = *(const float4*)(g + (size_t)row*ldA + c4);
        int off = (row*STRIDE + c4)*2;
        *(uint2*)(smHi+off) = make_uint2(pkhf2(v.x,v.y), pkhf2(v.z,v.w));
        *(uint2*)(smLo+off) = make_uint2(pkhf2(hres(v.x),hres(v.y)),
                                         pkhf2(hres(v.z),hres(v.w)));
    }
}
// rows x 128 fp32 -> fp16 single plane (Q / P / V operands)
template<int ROWS, int STRIDE>
__device__ __forceinline__ void ldconvH1(const float* __restrict__ g, int ldA,
                                         char* smHi, int tid){
    const int PER = (ROWS*32)/256;
#pragma unroll
    for (int i = 0; i < PER; i++){
        int idx = tid + i*256;
        int row = idx >> 5;
        int c4  = (idx & 31) << 2;
        float4 v = *(const float4*)(g + (size_t)row*ldA + c4);
        *(uint2*)(smHi + (row*STRIDE + c4)*2) =
            make_uint2(pkhf2(v.x,v.y), pkhf2(v.z,v.w));
    }
}

// 128x128-output warp step (proj, bf16x3): warp computes 32x64
template<int SA, int SB>
__device__ __forceinline__ void wstep(u32 Ah, u32 Al, u32 Bh, u32 Bl,
                                      int ks, int warp_m, int warp_n, int lane,
                                      float c[2][8][4]){
    const int rsel = lane & 15, ksel = (lane >> 4) << 3;
    const int kb = ks*16 + ksel;
    u32 ah[2][4], al[2][4], bh[4][4], bl[4][4];
#pragma unroll
    for (int mt = 0; mt < 2; mt++){
        u32 off = (u32)((warp_m*32 + mt*16 + rsel)*SA + kb)*2;
        ldmx4(ah[mt], Ah + off);
        ldmx4(al[mt], Al + off);
    }
#pragma unroll
    for (int p = 0; p < 4; p++){
        u32 off = (u32)((warp_n*64 + p*16 + rsel)*SB + kb)*2;
        ldmx4(bh[p], Bh + off);
        ldmx4(bl[p], Bl + off);
    }
#pragma unroll
    for (int mt = 0; mt < 2; mt++)
#pragma unroll
        for (int nt = 0; nt < 8; nt++){
            int p = nt >> 1, s = nt & 1;
            mma16816(c[mt][nt], ah[mt], bh[p][s], bh[p][2+s]);
            mma16816(c[mt][nt], ah[mt], bl[p][s], bl[p][2+s]);
            mma16816(c[mt][nt], al[mt], bh[p][s], bh[p][2+s]);
        }
}

// 64x128-output warp step (phase 1, fp16: A single, B hi+lo): warp 16x64
template<int SA, int SB>
__device__ __forceinline__ void wstep64h(u32 Ah, u32 Bh, u32 Bl,
                                         int ks, int warp_m, int warp_n, int lane,
                                         float c[8][4]){
    const int rsel = lane & 15, ksel = (lane >> 4) << 3;
    const int kb = ks*16 + ksel;
    u32 ah[4], bh[4][4], bl[4][4];
    ldmx4(ah, Ah + (u32)((warp_m*16 + rsel)*SA + kb)*2);
#pragma unroll
    for (int p = 0; p < 4; p++){
        u32 off = (u32)((warp_n*64 + p*16 + rsel)*SB + kb)*2;
        ldmx4(bh[p], Bh + off);
        ldmx4(bl[p], Bl + off);
    }
#pragma unroll
    for (int nt = 0; nt < 8; nt++){
        int p = nt >> 1, s = nt & 1;
        mma16816h(c[nt], ah, bh[p][s], bh[p][2+s]);
        mma16816h(c[nt], ah, bl[p][s], bl[p][2+s]);
    }
}

// 64x128-output warp step (phase 2, fp16: A single, B single): warp 16x64
template<int SA, int SB>
__device__ __forceinline__ void wstep64v(u32 Ah, u32 Bh,
                                         int ks, int warp_m, int warp_n, int lane,
                                         float c[8][4]){
    const int rsel = lane & 15, ksel = (lane >> 4) << 3;
    const int kb = ks*16 + ksel;
    u32 ah[4], bh[4][4];
    ldmx4(ah, Ah + (u32)((warp_m*16 + rsel)*SA + kb)*2);
#pragma unroll
    for (int p = 0; p < 4; p++)
        ldmx4(bh[p], Bh + (u32)((warp_n*64 + p*16 + rsel)*SB + kb)*2);
#pragma unroll
    for (int nt = 0; nt < 8; nt++){
        int p = nt >> 1, s = nt & 1;
        mma16816h(c[nt], ah, bh[p][s], bh[p][2+s]);
    }
}

// ---------------------------------------------------------------------------
// proj (bf16x3, 2 CTAs/SM, unchanged from R14).
// ---------------------------------------------------------------------------
#define PSTR 72
#define PTILE (128*PSTR*2)
#define PROJ_SM (4*PTILE)
__device__ __forceinline__ void proj_body(
    const float* __restrict__ A, const float* __restrict__ W,
    const float* __restrict__ bias, float* __restrict__ C,
    int M, int N, int K, int m0, int n0, char* sm)
{
    u32 sb = s2u(sm);
    const int tid = threadIdx.x, lane = tid & 31, wid = tid >> 5;
    const int warp_m = wid & 3, warp_n = wid >> 2;

    char* Ahp = sm;            char* Alp = sm + PTILE;
    char* Bhp = sm + 2*PTILE;  char* Blp = sm + 3*PTILE;
    const u32 Ah = sb, Al = sb + PTILE, Bh = sb + 2*PTILE, Bl = sb + 3*PTILE;

    float c[2][8][4];
#pragma unroll
    for (int i=0;i<2;i++) for (int j=0;j<8;j++) for (int q=0;q<4;q++) c[i][j][q]=0.f;

    const int NC = K/64;
    for (int kc = 0; kc < NC; kc++){
        ldconvG<128,64,PSTR>(A + (size_t)m0*K + kc*64, K, Ahp, Alp, tid);
        ldconvG<128,64,PSTR>(W + (size_t)n0*K + kc*64, K, Bhp, Blp, tid);
        __syncthreads();
#pragma unroll
        for (int ks = 0; ks < 4; ks++)
            wstep<PSTR,PSTR>(Ah, Al, Bh, Bl, ks, warp_m, warp_n, lane, c);
        __syncthreads();
    }

#pragma unroll
    for (int mt = 0; mt < 2; mt++)
#pragma unroll
        for (int rh = 0; rh < 2; rh++){
            int row = m0 + warp_m*32 + mt*16 + rh*8 + (lane >> 2);
#pragma unroll
            for (int nt = 0; nt < 8; nt++){
                int col = n0 + warp_n*64 + nt*8 + ((lane & 3) << 1);
                float2 o;
                o.x = c[mt][nt][rh*2+0] + __ldg(bias + col);
                o.y = c[mt][nt][rh*2+1] + __ldg(bias + col + 1);
                *(float2*)(C + (size_t)row*N + col) = o;
            }
        }
}

__global__ void __launch_bounds__(256,2) proj_mma(
    const float* __restrict__ A, const float* __restrict__ W,
    const float* __restrict__ bias, float* __restrict__ C,
    int M, int N, int K)
{
    extern __shared__ char sm[];
    proj_body(A, W, bias, C, M, N, K, blockIdx.y << 7, blockIdx.x << 7, sm);
}

__global__ void __launch_bounds__(256,2) proj_mma_kv(
    const float* __restrict__ kin, const float* __restrict__ vin,
    const float* __restrict__ Wk, const float* __restrict__ bk, float* __restrict__ kh,
    const float* __restrict__ Wv, const float* __restrict__ bv, float* __restrict__ vh,
    int M, int K)
{
    extern __shared__ char sm[];
    if (blockIdx.x == 0)
        proj_body(kin, Wk, bk, kh, M, DKc, K, blockIdx.y << 7, 0, sm);
    else
        proj_body(vin, Wv, bv, vh, M, DVc, K, blockIdx.y << 7, 0, sm);
}

// vh [b,k,d] -> vT [b,d,k]
__global__ void transpose_v(const float* __restrict__ vh, float* __restrict__ vT){
    __shared__ float t[32][33];
    int b = blockIdx.z;
    int k0 = blockIdx.x*32, d0 = blockIdx.y*32;
    int x = threadIdx.x, y = threadIdx.y;
#pragma unroll
    for (int i = 0; i < 32; i += 8)
        t[y+i][x] = vh[(size_t)(b*NKc + k0 + y + i)*DVc + d0 + x];
    __syncthreads();
#pragma unroll
    for (int i = 0; i < 32; i += 8)
        vT[((size_t)b*DVc + d0 + y + i)*NKc + k0 + x] = t[x][y+i];
}

// ---------------------------------------------------------------------------
// fused attention (R14 structure): fp16, Q/P single plane, K hi+lo,
// V single plane (NEW). 2 CTAs/SM.
// ---------------------------------------------------------------------------
#define SSTR 136
#define QTILE (64*SSTR*2)    // 17408
#define KTILE (128*SSTR*2)   // 34816 per plane
#define FUS_SM (QTILE + 2*KTILE)  // 87040
__global__ void __launch_bounds__(256,2) fused_attn(
    const float* __restrict__ qh, const float* __restrict__ kh,
    const float* __restrict__ vT, const float* __restrict__ mask,
    float* __restrict__ attn, float* __restrict__ outh)
{
    extern __shared__ char sm[];
    __shared__ float Ms[64], Li[64];
    __shared__ float sM2[2][64], sL2[2][64];
    u32 sb = s2u(sm);
    const int tid = threadIdx.x, lane = tid & 31, wid = tid >> 5;
    const int warp_m = wid & 3, warp_n = wid >> 2;
    const int q0 = blockIdx.x << 6;
    const int hb = blockIdx.y, b = hb >> 3, h = hb & 7;

    char* Ahp = sm;                 // Q, later P (fp16 single plane)
    char* Bhp = sm + QTILE;         // K hi / V
    char* Blp = sm + QTILE + KTILE; // K lo
    const u32 Ah = sb, Bh = sb + QTILE, Bl = sb + QTILE + KTILE;

    const float* qbase = qh + (size_t)(b*NQc + q0)*Dc + h*DKc;
    const float* kbase = kh + (size_t)b*NKc*DKc;
    const float* vbase = vT + (size_t)b*DVc*NKc;
    float* abase = attn + ((size_t)(h*Bc + b)*NQc + q0)*NKc;

    // ---- Phase 1 ----
    ldconvH1<64,SSTR>(qbase, Dc, Ahp, tid);

    const float scale = 0.08838834764831845f;
    float rm_[2] = {-1e30f, -1e30f}, rl_[2] = {0.f, 0.f};

    for (int kt = 0; kt < KTILES; kt++){
        ldconvH2<128,SSTR>(kbase + (size_t)(kt*128)*DKc, DKc, Bhp, Blp, tid);
        __syncthreads();

        float c[8][4];
#pragma unroll
        for (int j=0;j<8;j++) for (int q=0;q<4;q++) c[j][q]=0.f;
#pragma unroll
        for (int ks = 0; ks < 8; ks++)
            wstep64h<SSTR,SSTR>(Ah, Bh, Bl, ks, warp_m, warp_n, lane, c);

#pragma unroll
        for (int rh = 0; rh < 2; rh++){
            int rowl = warp_m*16 + rh*8 + (lane >> 2);
            const float* mrow = mask + ((size_t)b*NQc + q0 + rowl)*NKc + kt*128;
            float* arow = abase + (size_t)rowl*NKc + kt*128;
            float sv[16];
            float mloc = -1e30f;
#pragma unroll
            for (int nt = 0; nt < 8; nt++){
                int col = warp_n*64 + nt*8 + ((lane & 3) << 1);
                float2 mv = *(const float2*)(mrow + col);
                sv[2*nt+0] = fmaf(c[nt][rh*2+0], scale, mv.x);
                sv[2*nt+1] = fmaf(c[nt][rh*2+1], scale, mv.y);
                *(float2*)(arow + col) = make_float2(sv[2*nt+0], sv[2*nt+1]);
                mloc = fmaxf(mloc, fmaxf(sv[2*nt+0], sv[2*nt+1]));
            }
#pragma unroll
            for (int off = 1; off <= 2; off <<= 1)
                mloc = fmaxf(mloc, __shfl_xor_sync(0xFFFFFFFFu, mloc, off));
            float let = 0.f;
#pragma unroll
            for (int nt = 0; nt < 8; nt++){
                let += __expf(sv[2*nt+0] - mloc);
                let += __expf(sv[2*nt+1] - mloc);
            }
#pragma unroll
            for (int off = 1; off <= 2; off <<= 1)
                let += __shfl_xor_sync(0xFFFFFFFFu, let, off);
            float nm = fmaxf(rm_[rh], mloc);
            rl_[rh] = rl_[rh]*__expf(rm_[rh] - nm) + let*__expf(mloc - nm);
            rm_[rh] = nm;
        }
        __syncthreads();
    }

    // ---- stat combine ----
#pragma unroll
    for (int rh = 0; rh < 2; rh++){
        int rowl = warp_m*16 + rh*8 + (lane >> 2);
        if ((lane & 3) == 0){
            sM2[warp_n][rowl] = rm_[rh];
            sL2[warp_n][rowl] = rl_[rh];
        }
    }
    __syncthreads();
    if (tid < 64){
        float m0 = sM2[0][tid], m1 = sM2[1][tid];
        float M = fmaxf(m0, m1);
        float L = sL2[0][tid]*__expf(m0 - M) + sL2[1][tid]*__expf(m1 - M);
        Ms[tid] = M; Li[tid] = 1.0f / L;
    }
    __syncthreads();

    // ---- Phase 2: P = exp(s - M)*Li; P single plane; V single plane ----
    float c[8][4];
#pragma unroll
    for (int j=0;j<8;j++) for (int q=0;q<4;q++) c[j][q]=0.f;

    for (int kt = 0; kt < KTILES; kt++){
#pragma unroll
        for (int i = 0; i < 8; i++){
            int idx = tid + i*256;
            int row = idx >> 5, c4 = (idx & 31) << 2;
            float* ap = abase + (size_t)row*NKc + kt*128 + c4;
            float4 s = *(float4*)ap;
            float mm = Ms[row], li = Li[row];
            float4 p;
            p.x = __expf(s.x - mm)*li; p.y = __expf(s.y - mm)*li;
            p.z = __expf(s.z - mm)*li; p.w = __expf(s.w - mm)*li;
            *(float4*)ap = p;
            *(uint2*)(Ahp + (row*SSTR + c4)*2) =
                make_uint2(pkhf2(p.x,p.y), pkhf2(p.z,p.w));
        }
        ldconvH1<128,SSTR>(vbase + kt*128, NKc, Bhp, tid);
        __syncthreads();
#pragma unroll
        for (int ks = 0; ks < 8; ks++)
            wstep64v<SSTR,SSTR>(Ah, Bh, ks, warp_m, warp_n, lane, c);
        __syncthreads();
    }

#pragma unroll
    for (int rh = 0; rh < 2; rh++){
        int row = q0 + warp_m*16 + rh*8 + (lane >> 2);
        float* op = outh + (size_t)(b*NQc + row)*(Hc*DVc) + h*DVc;
#pragma unroll
        for (int nt = 0; nt < 8; nt++){
            int col = warp_n*64 + nt*8 + ((lane & 3) << 1);
            *(float2*)(op + col) = make_float2(c[nt][rh*2+0], c[nt][rh*2+1]);
        }
    }
}

// ---------------------------------------------------------------------------
extern "C" void kernel_launch(void* const* d_in, const int* in_sizes, int n_in,
                              void* d_out, int out_size)
{
    const float* q    = (const float*)d_in[0];
    const float* k    = (const float*)d_in[1];
    const float* v    = (const float*)d_in[2];
    const float* mask = (const float*)d_in[3];
    const float* Wq   = (const float*)d_in[4];
    const float* bq   = (const float*)d_in[5];
    const float* Wk   = (const float*)d_in[6];
    const float* bk   = (const float*)d_in[7];
    const float* Wv   = (const float*)d_in[8];
    const float* bv   = (const float*)d_in[9];
    const float* Wo   = (const float*)d_in[10];
    const float* bo   = (const float*)d_in[11];

    float* attn = (float*)d_out;
    float* outp = attn + (size_t)HBc*NQc*NKc;

    float *qh,*kh,*vh,*vT,*outh;
    cudaGetSymbolAddress((void**)&qh,   g_qh);
    cudaGetSymbolAddress((void**)&kh,   g_kh);
    cudaGetSymbolAddress((void**)&vh,   g_vh);
    cudaGetSymbolAddress((void**)&vT,   g_vT);
    cudaGetSymbolAddress((void**)&outh, g_outh);

    cudaFuncSetAttribute(proj_mma,    cudaFuncAttributeMaxDynamicSharedMemorySize, PROJ_SM);
    cudaFuncSetAttribute(proj_mma_kv, cudaFuncAttributeMaxDynamicSharedMemorySize, PROJ_SM);
    cudaFuncSetAttribute(fused_attn,  cudaFuncAttributeMaxDynamicSharedMemorySize, FUS_SM);

    dim3 blk(256);
    const int Mr = Bc*NQc;   // 8192

    proj_mma<<<dim3((Hc*DKc)/128, Mr/128), blk, PROJ_SM>>>(q, Wq, bq, qh, Mr, Hc*DKc, Dc);
    proj_mma_kv<<<dim3(2, Mr/128), blk, PROJ_SM>>>(k, v, Wk, bk, kh, Wv, bv, vh, Mr, Dc);

    transpose_v<<<dim3(NKc/32, DVc/32, Bc), dim3(32,8)>>>(vh, vT);

    fused_attn<<<dim3(NQc/64, HBc), blk, FUS_SM>>>(qh, kh, vT, mask, attn, outh);

    proj_mma<<<dim3(DOc/128, Mr/128), blk, PROJ_SM>>>(outh, Wo, bo, outp, Mr, DOc, Hc*DVc);
}